// round 9
// baseline (speedup 1.0000x reference)
#include <cuda_runtime.h>
#include <cuda_fp16.h>
#include <cstdint>
#include <cstddef>

#define BATCH   2048
#define HIDDEN  1024
#define FFN     4096
#define NEXP    8
#define TOPK    2
#define NPAIR   (BATCH * TOPK)
#define MAXMB   64
#define KSPLIT  4

// ---------------- device scratch ----------------
__device__ int    g_off[NEXP + 1];
__device__ int    g_num_mb;
__device__ int    g_blk_e[MAXMB];
__device__ int    g_blk_r0[MAXMB];
__device__ int    g_tok[NPAIR];
__device__ int    g_ppos[NPAIR];
__device__ float  g_w[NPAIR];
__device__ __half g_xh[(size_t)BATCH * HIDDEN];                // 4 MiB fp16 x
__device__ __half g_hbuf[(size_t)NPAIR * FFN];                 // 32 MiB fp16
__device__ float  g_ybuf[(size_t)KSPLIT * NPAIR * HIDDEN];     // 64 MiB fp32

// ---------------- helpers ----------------
__device__ __forceinline__ uint32_t smem_u32(const void* p) {
    uint32_t a;
    asm("{ .reg .u64 t; cvta.to.shared.u64 t, %1; cvt.u32.u64 %0, t; }" : "=r"(a) : "l"(p));
    return a;
}
__device__ __forceinline__ uint32_t pk_f16x2(float lo, float hi) {
    uint32_t r;
    asm("cvt.rn.f16x2.f32 %0, %1, %2;" : "=r"(r) : "f"(hi), "f"(lo));
    return r;
}
__device__ __forceinline__ void ldmx4(uint32_t* d, uint32_t addr) {
    asm volatile("ldmatrix.sync.aligned.m8n8.x4.shared.b16 {%0,%1,%2,%3}, [%4];"
                 : "=r"(d[0]), "=r"(d[1]), "=r"(d[2]), "=r"(d[3]) : "r"(addr));
}
__device__ __forceinline__ void ldmx4t(uint32_t* d, uint32_t addr) {
    asm volatile("ldmatrix.sync.aligned.m8n8.x4.trans.shared.b16 {%0,%1,%2,%3}, [%4];"
                 : "=r"(d[0]), "=r"(d[1]), "=r"(d[2]), "=r"(d[3]) : "r"(addr));
}
__device__ __forceinline__ void mma_f16(float* c, const uint32_t* a, uint32_t b0, uint32_t b1) {
    asm volatile(
        "mma.sync.aligned.m16n8k16.row.col.f32.f16.f16.f32 "
        "{%0,%1,%2,%3}, {%4,%5,%6,%7}, {%8,%9}, {%0,%1,%2,%3};"
        : "+f"(c[0]), "+f"(c[1]), "+f"(c[2]), "+f"(c[3])
        : "r"(a[0]), "r"(a[1]), "r"(a[2]), "r"(a[3]), "r"(b0), "r"(b1));
}
__device__ __forceinline__ void cpasync16(uint32_t dst, const void* src) {
    asm volatile("cp.async.cg.shared.global [%0], [%1], 16;" :: "r"(dst), "l"(src));
}

// smem per stage (24 KiB):
//   As: 8 KiB fp16 [128 m][32 k]: addr(m,kc8) = (m>>1)*128 + (((m&1)*4+kc)^((m>>1)&7))*16
//   Bs: 16 KiB at +8192 fp16 [32 k][256 n]: addr(k,nc8) = k*512 + ((nc^(k&7)))*16
__device__ __forceinline__ uint32_t a_addr(int m, int kc) {
    return (uint32_t)((m >> 1) * 128 + (((((m & 1) << 2) | kc) ^ ((m >> 1) & 7)) << 4));
}
__device__ __forceinline__ uint32_t b_addr(int k, int nc) {
    return (uint32_t)(8192 + k * 512 + ((nc ^ (k & 7)) << 4));
}

// ---------------- routing (128-row M-blocks) ----------------
__global__ void route_kernel(const int* __restrict__ idx32, const float* __restrict__ rw) {
    __shared__ int s_cnt[NEXP];
    __shared__ int s_fill[NEXP];
    __shared__ int s_off[NEXP + 1];
    __shared__ int s_is64;
    const int tid = threadIdx.x;

    if (tid < NEXP) { s_cnt[tid] = 0; s_fill[tid] = 0; }
    if (tid == 0) {
        int any = 0;
        for (int i = 0; i < 64; i++) any |= idx32[2 * i + 1];
        s_is64 = (any == 0) ? 1 : 0;
    }
    __syncthreads();
    const int is64 = s_is64;

    for (int i = tid; i < NPAIR; i += blockDim.x) {
        int e = is64 ? idx32[2 * i] : idx32[i];
        atomicAdd(&s_cnt[e], 1);
    }
    __syncthreads();

    if (tid == 0) {
        int acc = 0, nb = 0;
        s_off[0] = 0;
        for (int e = 0; e < NEXP; e++) {
            for (int r = 0; r < s_cnt[e]; r += 128) {
                g_blk_e[nb] = e; g_blk_r0[nb] = acc + r; nb++;
            }
            acc += s_cnt[e];
            s_off[e + 1] = acc;
        }
        g_num_mb = nb;
        for (int e = 0; e <= NEXP; e++) g_off[e] = s_off[e];
    }
    __syncthreads();

    for (int i = tid; i < NPAIR; i += blockDim.x) {
        int e = is64 ? idx32[2 * i] : idx32[i];
        int pos = s_off[e] + atomicAdd(&s_fill[e], 1);
        g_tok[pos] = i >> 1;
        g_w[pos]   = rw[i];
        g_ppos[i]  = pos;
    }
}

// ---------------- x -> fp16 ----------------
__global__ void xconv_kernel(const float* __restrict__ x) {
    const size_t i = ((size_t)blockIdx.x * blockDim.x + threadIdx.x) * 8;
    float4 v0 = *reinterpret_cast<const float4*>(x + i);
    float4 v1 = *reinterpret_cast<const float4*>(x + i + 4);
    uint4 o;
    o.x = pk_f16x2(v0.x, v0.y); o.y = pk_f16x2(v0.z, v0.w);
    o.z = pk_f16x2(v1.x, v1.y); o.w = pk_f16x2(v1.z, v1.w);
    *reinterpret_cast<uint4*>(&g_xh[i]) = o;
}

// ---------------- grouped GEMM (fp16 mma, fp32 accum) ----------------
// MODE 1: h[p] = silu(xh[tok(p)] @ w1[e])                     -> g_hbuf (fp16)
// MODE 2: yb[z][p] = w(p)*(h[p, z*1024:+1024] @ w2[e][...])   -> g_ybuf
// CTA tile 128(M) x 256(N), k-tile 32, K=1024 per CTA (32 k-tiles).
// 256 threads = 8 warps (2M x 4N), warp tile 64x64. 1 CTA/SM.
// A (fp16) via cp.async; B (fp32 weights) LDG -> packed fp16x2 -> STS.
// Compute loop = R3 structure (per-ks frag loads, no cross-ks prefetch).
template <int MODE>
__global__ __launch_bounds__(256, 1)
void moe_mma(const float* __restrict__ W) {
    constexpr int NDIM  = (MODE == 1) ? FFN : HIDDEN;
    constexpr int KFULL = (MODE == 1) ? HIDDEN : FFN;

    __shared__ __align__(128) uint8_t smbuf[2][24576];

    const int mb = blockIdx.x;
    if (mb >= g_num_mb) return;
    const int e      = g_blk_e[mb];
    const int row0   = g_blk_r0[mb];
    const int rowEnd = g_off[e + 1];
    const int n0     = blockIdx.y * 256;
    const int kbase  = (MODE == 2) ? blockIdx.z * 1024 : 0;
    const float* __restrict__ We =
        W + (size_t)e * KFULL * NDIM + (size_t)kbase * NDIM;

    const int tid = threadIdx.x, lane = tid & 31, warp = tid >> 5;
    const int wm = (warp & 1) * 64, wn = (warp >> 1) * 64;
    const uint32_t smb = smem_u32(&smbuf[0][0]);

    // ---- A staging via cp.async: 2 units/thread (1 row x 8 k = 16B) ----
    const __half* aP[2];
    uint32_t aoff[2];
#pragma unroll
    for (int i = 0; i < 2; i++) {
        int u = tid + i * 256;          // 0..511
        int m = u >> 2, kc = u & 3;
        int p = row0 + m; if (p >= rowEnd) p = rowEnd - 1;
        aP[i] = ((MODE == 1) ? (g_xh + (size_t)g_tok[p] * HIDDEN)
                             : (g_hbuf + (size_t)p * FFN + kbase)) + kc * 8;
        aoff[i] = a_addr(m, kc);
    }
    // ---- B staging: 4 units/thread (1 k x 8 n) ----
    const float* bPf[4];
    uint32_t boff[4];
#pragma unroll
    for (int i = 0; i < 4; i++) {
        int u = tid + i * 256;          // 0..1023
        int k = u >> 5, nc = u & 31;
        bPf[i] = We + (size_t)k * NDIM + n0 + nc * 8;
        boff[i] = b_addr(k, nc);
    }

    // ---- fragment base addresses (ks=0); ks=1: A ^32, B +8192 ----
    const int g = lane >> 3, r = lane & 7;
    uint32_t aFrag[4], bFrag[4];
#pragma unroll
    for (int mt = 0; mt < 4; mt++)
        aFrag[mt] = a_addr(wm + mt * 16 + (g & 1) * 8 + r, (g >> 1));
#pragma unroll
    for (int ntp = 0; ntp < 4; ntp++)
        bFrag[ntp] = b_addr((g & 1) * 8 + r, (wn >> 3) + ntp * 2 + (g >> 1));

    float C[4][8][4];
#pragma unroll
    for (int a = 0; a < 4; a++)
#pragma unroll
        for (int b = 0; b < 8; b++)
#pragma unroll
            for (int d = 0; d < 4; d++) C[a][b][d] = 0.f;

    uint4 b_st[4];    // packed fp16x2 B staging (16 regs)

    auto cpA = [&](int kt, int buf) {
        const uint32_t sb = smb + buf * 24576;
#pragma unroll
        for (int i = 0; i < 2; i++)
            cpasync16(sb + aoff[i], aP[i] + kt * 32);
        asm volatile("cp.async.commit_group;" ::: "memory");
    };
    auto ldgB = [&](int kt) {
        const size_t bk = (size_t)kt * 32 * NDIM;
#pragma unroll
        for (int i = 0; i < 4; i++) {
            float4 v0 = *reinterpret_cast<const float4*>(bPf[i] + bk);
            float4 v1 = *reinterpret_cast<const float4*>(bPf[i] + bk + 4);
            b_st[i].x = pk_f16x2(v0.x, v0.y);
            b_st[i].y = pk_f16x2(v0.z, v0.w);
            b_st[i].z = pk_f16x2(v1.x, v1.y);
            b_st[i].w = pk_f16x2(v1.z, v1.w);
        }
    };
    auto stsB = [&](int buf) {
        const uint32_t sb = smb + buf * 24576;
#pragma unroll
        for (int i = 0; i < 4; i++)
            asm volatile("st.shared.v4.b32 [%0], {%1,%2,%3,%4};"
                :: "r"(sb + boff[i]), "r"(b_st[i].x), "r"(b_st[i].y),
                   "r"(b_st[i].z), "r"(b_st[i].w));
    };
    auto compute = [&](int buf) {
        const uint32_t sb = smb + buf * 24576;
#pragma unroll
        for (int ks = 0; ks < 2; ks++) {
            uint32_t af[4][4];
#pragma unroll
            for (int mt = 0; mt < 4; mt++)
                ldmx4(af[mt], sb + (aFrag[mt] ^ (ks ? 32u : 0u)));
            uint32_t bf[4][4];
#pragma unroll
            for (int ntp = 0; ntp < 4; ntp++)
                ldmx4t(bf[ntp], sb + bFrag[ntp] + ks * 8192);
#pragma unroll
            for (int mt = 0; mt < 4; mt++)
#pragma unroll
                for (int nt = 0; nt < 8; nt++)
                    mma_f16(C[mt][nt], af[mt], bf[nt >> 1][(nt & 1) * 2],
                            bf[nt >> 1][(nt & 1) * 2 + 1]);
        }
    };

    // ---- pipelined main loop (32 k-tiles) ----
    cpA(0, 0);
    ldgB(0);
    stsB(0);
    asm volatile("cp.async.wait_group 0;" ::: "memory");
    __syncthreads();
#pragma unroll 1
    for (int kt = 0; kt < 32; kt++) {
        const int buf = kt & 1;
        if (kt < 31) { ldgB(kt + 1); cpA(kt + 1, buf ^ 1); }
        compute(buf);
        if (kt < 31) stsB(buf ^ 1);
        asm volatile("cp.async.wait_group 0;" ::: "memory");
        __syncthreads();
    }

    // ---- epilogue ----
    const int grp = lane >> 2, tg = lane & 3;
#pragma unroll
    for (int mt = 0; mt < 4; mt++) {
#pragma unroll
        for (int half = 0; half < 2; half++) {
            const int rowm = wm + mt * 16 + grp + half * 8;
            const int p = row0 + rowm;
            if (p < rowEnd) {
                float wgt = 0.f;
                if (MODE == 2) wgt = g_w[p];
#pragma unroll
                for (int nt = 0; nt < 8; nt++) {
                    float v0 = C[mt][nt][half * 2 + 0];
                    float v1 = C[mt][nt][half * 2 + 1];
                    const int col = n0 + wn + nt * 8 + 2 * tg;
                    if (MODE == 1) {
                        float s0 = v0 / (1.f + __expf(-v0));
                        float s1 = v1 / (1.f + __expf(-v1));
                        *reinterpret_cast<uint32_t*>(&g_hbuf[(size_t)p * FFN + col]) =
                            pk_f16x2(s0, s1);
                    } else {
                        float* dst = g_ybuf +
                            ((size_t)blockIdx.z * NPAIR + p) * HIDDEN + col;
                        *reinterpret_cast<float2*>(dst) = make_float2(v0 * wgt, v1 * wgt);
                    }
                }
            }
        }
    }
}

// ---------------- combine ----------------
__global__ void combine_kernel(float* __restrict__ out) {
    const int t = blockIdx.x;
    const int c = threadIdx.x * 4;
    const int p0 = g_ppos[2 * t], p1 = g_ppos[2 * t + 1];
    float4 acc = make_float4(0.f, 0.f, 0.f, 0.f);
#pragma unroll
    for (int s = 0; s < KSPLIT; s++) {
        const float4 a = *reinterpret_cast<const float4*>(
            g_ybuf + ((size_t)s * NPAIR + p0) * HIDDEN + c);
        const float4 b = *reinterpret_cast<const float4*>(
            g_ybuf + ((size_t)s * NPAIR + p1) * HIDDEN + c);
        acc.x += a.x + b.x; acc.y += a.y + b.y;
        acc.z += a.z + b.z; acc.w += a.w + b.w;
    }
    *reinterpret_cast<float4*>(out + (size_t)t * HIDDEN + c) = acc;
}

// ---------------- launch ----------------
extern "C" void kernel_launch(void* const* d_in, const int* in_sizes, int n_in,
                              void* d_out, int out_size) {
    const float* x   = (const float*)d_in[0];
    const float* rw  = (const float*)d_in[1];
    const float* w1  = (const float*)d_in[2];
    const float* w2  = (const float*)d_in[3];
    const int*   idx = (const int*)d_in[4];
    float* out = (float*)d_out;

    route_kernel<<<1, 256>>>(idx, rw);
    xconv_kernel<<<(BATCH * HIDDEN) / (256 * 8), 256>>>(x);
    moe_mma<1><<<dim3(40, FFN / 256, 1), 256>>>(w1);
    moe_mma<2><<<dim3(40, HIDDEN / 256, KSPLIT), 256>>>(w2);
    combine_kernel<<<BATCH, 256>>>(out);
}

// round 10
// speedup vs baseline: 1.3400x; 1.3400x over previous
#include <cuda_runtime.h>
#include <cuda_fp16.h>
#include <cstdint>
#include <cstddef>

#define BATCH   2048
#define HIDDEN  1024
#define FFN     4096
#define NEXP    8
#define TOPK    2
#define NPAIR   (BATCH * TOPK)
#define MAXMB   64
#define KSPLIT  4

// ---------------- device scratch ----------------
__device__ int    g_off[NEXP + 1];
__device__ int    g_num_mb;
__device__ int    g_blk_e[MAXMB];
__device__ int    g_blk_r0[MAXMB];
__device__ int    g_tok[NPAIR];
__device__ int    g_ppos[NPAIR];
__device__ float  g_w[NPAIR];
__device__ __half g_xh[(size_t)BATCH * HIDDEN];                // 4 MiB
__device__ __half g_w1h[(size_t)NEXP * HIDDEN * FFN];          // 64 MiB fp16 w1
__device__ __half g_w2h[(size_t)NEXP * FFN * HIDDEN];          // 64 MiB fp16 w2
__device__ __half g_hbuf[(size_t)NPAIR * FFN];                 // 32 MiB
__device__ float  g_ybuf[(size_t)KSPLIT * NPAIR * HIDDEN];     // 64 MiB

// ---------------- helpers ----------------
__device__ __forceinline__ uint32_t smem_u32(const void* p) {
    uint32_t a;
    asm("{ .reg .u64 t; cvta.to.shared.u64 t, %1; cvt.u32.u64 %0, t; }" : "=r"(a) : "l"(p));
    return a;
}
__device__ __forceinline__ uint32_t pk_f16x2(float lo, float hi) {
    uint32_t r;
    asm("cvt.rn.f16x2.f32 %0, %1, %2;" : "=r"(r) : "f"(hi), "f"(lo));
    return r;
}
__device__ __forceinline__ void ldmx4(uint32_t* d, uint32_t addr) {
    asm volatile("ldmatrix.sync.aligned.m8n8.x4.shared.b16 {%0,%1,%2,%3}, [%4];"
                 : "=r"(d[0]), "=r"(d[1]), "=r"(d[2]), "=r"(d[3]) : "r"(addr));
}
__device__ __forceinline__ void ldmx4t(uint32_t* d, uint32_t addr) {
    asm volatile("ldmatrix.sync.aligned.m8n8.x4.trans.shared.b16 {%0,%1,%2,%3}, [%4];"
                 : "=r"(d[0]), "=r"(d[1]), "=r"(d[2]), "=r"(d[3]) : "r"(addr));
}
__device__ __forceinline__ void mma_f16(float* c, const uint32_t* a, uint32_t b0, uint32_t b1) {
    asm volatile(
        "mma.sync.aligned.m16n8k16.row.col.f32.f16.f16.f32 "
        "{%0,%1,%2,%3}, {%4,%5,%6,%7}, {%8,%9}, {%0,%1,%2,%3};"
        : "+f"(c[0]), "+f"(c[1]), "+f"(c[2]), "+f"(c[3])
        : "r"(a[0]), "r"(a[1]), "r"(a[2]), "r"(a[3]), "r"(b0), "r"(b1));
}
__device__ __forceinline__ void cpasync16(uint32_t dst, const void* src) {
    asm volatile("cp.async.cg.shared.global [%0], [%1], 16;" :: "r"(dst), "l"(src));
}

// smem per stage (24 KiB):
//   As: 8 KiB fp16 [128 m][32 k]
//   Bs: 16 KiB at +8192 fp16 [32 k][256 n]
__device__ __forceinline__ uint32_t a_addr(int m, int kc) {
    return (uint32_t)((m >> 1) * 128 + (((((m & 1) << 2) | kc) ^ ((m >> 1) & 7)) << 4));
}
__device__ __forceinline__ uint32_t b_addr(int k, int nc) {
    return (uint32_t)(8192 + k * 512 + ((nc ^ (k & 7)) << 4));
}
#define STAGE_B 24576
#define NSTAGE  4
#define SMEM_TOTAL (NSTAGE * STAGE_B)

// ---------------- routing (128-row M-blocks) ----------------
__global__ void route_kernel(const int* __restrict__ idx32, const float* __restrict__ rw) {
    __shared__ int s_cnt[NEXP];
    __shared__ int s_fill[NEXP];
    __shared__ int s_off[NEXP + 1];
    __shared__ int s_is64;
    const int tid = threadIdx.x;

    if (tid < NEXP) { s_cnt[tid] = 0; s_fill[tid] = 0; }
    if (tid == 0) {
        int any = 0;
        for (int i = 0; i < 64; i++) any |= idx32[2 * i + 1];
        s_is64 = (any == 0) ? 1 : 0;
    }
    __syncthreads();
    const int is64 = s_is64;

    for (int i = tid; i < NPAIR; i += blockDim.x) {
        int e = is64 ? idx32[2 * i] : idx32[i];
        atomicAdd(&s_cnt[e], 1);
    }
    __syncthreads();

    if (tid == 0) {
        int acc = 0, nb = 0;
        s_off[0] = 0;
        for (int e = 0; e < NEXP; e++) {
            for (int r = 0; r < s_cnt[e]; r += 128) {
                g_blk_e[nb] = e; g_blk_r0[nb] = acc + r; nb++;
            }
            acc += s_cnt[e];
            s_off[e + 1] = acc;
        }
        g_num_mb = nb;
        for (int e = 0; e <= NEXP; e++) g_off[e] = s_off[e];
    }
    __syncthreads();

    for (int i = tid; i < NPAIR; i += blockDim.x) {
        int e = is64 ? idx32[2 * i] : idx32[i];
        int pos = s_off[e] + atomicAdd(&s_fill[e], 1);
        g_tok[pos] = i >> 1;
        g_w[pos]   = rw[i];
        g_ppos[i]  = pos;
    }
}

// ---------------- x -> fp16 ----------------
__global__ void xconv_kernel(const float* __restrict__ x) {
    const size_t i = ((size_t)blockIdx.x * blockDim.x + threadIdx.x) * 8;
    float4 v0 = *reinterpret_cast<const float4*>(x + i);
    float4 v1 = *reinterpret_cast<const float4*>(x + i + 4);
    uint4 o;
    o.x = pk_f16x2(v0.x, v0.y); o.y = pk_f16x2(v0.z, v0.w);
    o.z = pk_f16x2(v1.x, v1.y); o.w = pk_f16x2(v1.z, v1.w);
    *reinterpret_cast<uint4*>(&g_xh[i]) = o;
}

// ---------------- w1 -> fp16 (8,388,608 float4 total) ----------------
__global__ void w1conv_kernel(const float* __restrict__ w) {
    const size_t i = (size_t)blockIdx.x * 1024 + threadIdx.x;
    const float4* s = reinterpret_cast<const float4*>(w);
    uint2* d = reinterpret_cast<uint2*>(g_w1h);
#pragma unroll
    for (int j = 0; j < 4; j++) {
        float4 v = s[i + j * 256];
        uint2 o;
        o.x = pk_f16x2(v.x, v.y); o.y = pk_f16x2(v.z, v.w);
        d[i + j * 256] = o;
    }
}

// ---------------- pure-fp16 grouped GEMM, 4-stage cp.async ----------------
// MODE 1: h[p] = silu(xh[tok(p)] @ w1h[e]); also blockIdx.x>=40 => convert w2.
// MODE 2: yb[z][p] = w(p)*(hbuf[p, z*1024:+1024] @ w2h[e][...]).
// CTA tile 128(M) x 256(N), k-tile 32, KT=32 (K=1024/CTA). 256 thr = 8 warps
// (2M x 4N), warp tile 64x64. 1 CTA/SM. All operands via cp.async (fp16 src).
template <int MODE>
__global__ __launch_bounds__(256, 1)
void moe_fp16(const float* __restrict__ Wconv) {
    constexpr int NDIM = (MODE == 1) ? FFN : HIDDEN;
    constexpr int KT = 32;

    // -------- fused w2 converter blocks (GEMM1 grid only) --------
    if (MODE == 1 && blockIdx.x >= 40) {
        const int slice = (blockIdx.x - 40) + 16 * blockIdx.y;     // 0..255
        const size_t base4 = (size_t)slice * 32768;                // float4 units
        const float4* s = reinterpret_cast<const float4*>(Wconv) + base4;
        uint2* d = reinterpret_cast<uint2*>(g_w2h) + base4;
        for (int i = threadIdx.x; i < 32768; i += 256) {
            float4 v = s[i];
            uint2 o;
            o.x = pk_f16x2(v.x, v.y); o.y = pk_f16x2(v.z, v.w);
            d[i] = o;
        }
        return;
    }

    extern __shared__ __align__(128) uint8_t sm[];

    const int mb = blockIdx.x;
    if (mb >= g_num_mb) return;
    const int e      = g_blk_e[mb];
    const int row0   = g_blk_r0[mb];
    const int rowEnd = g_off[e + 1];
    const int n0     = blockIdx.y * 256;
    const int kbase  = (MODE == 2) ? blockIdx.z * 1024 : 0;
    const __half* __restrict__ Wh =
        ((MODE == 1) ? g_w1h : g_w2h) + (size_t)e * ((MODE == 1) ? HIDDEN : FFN) * NDIM
        + (size_t)kbase * NDIM;

    const int tid = threadIdx.x, lane = tid & 31, warp = tid >> 5;
    const int wm = (warp & 1) * 64, wn = (warp >> 1) * 64;
    const uint32_t smb = smem_u32(sm);

    // ---- A cp.async: 2 units/thread (1 row x 8 k = 16B) ----
    const __half* aP[2];
    uint32_t aoff[2];
#pragma unroll
    for (int i = 0; i < 2; i++) {
        int u = tid + i * 256;            // 0..511
        int m = u >> 2, kc = u & 3;
        int p = row0 + m; if (p >= rowEnd) p = rowEnd - 1;
        aP[i] = ((MODE == 1) ? (g_xh + (size_t)g_tok[p] * HIDDEN)
                             : (g_hbuf + (size_t)p * FFN + kbase)) + kc * 8;
        aoff[i] = a_addr(m, kc);
    }
    // ---- B cp.async: 4 units/thread (1 k x 8 n = 16B) ----
    const __half* bP[4];
    uint32_t boff[4];
#pragma unroll
    for (int i = 0; i < 4; i++) {
        int u = tid + i * 256;            // 0..1023
        int k = u >> 5, nc = u & 31;
        bP[i] = Wh + (size_t)k * NDIM + n0 + nc * 8;
        boff[i] = b_addr(k, nc);
    }

    // ---- fragment base addresses (ks=0); ks=1: A ^32, B +8192 ----
    const int g = lane >> 3, r = lane & 7;
    uint32_t aFrag[4], bFrag[4];
#pragma unroll
    for (int mt = 0; mt < 4; mt++)
        aFrag[mt] = a_addr(wm + mt * 16 + (g & 1) * 8 + r, (g >> 1));
#pragma unroll
    for (int ntp = 0; ntp < 4; ntp++)
        bFrag[ntp] = b_addr((g & 1) * 8 + r, (wn >> 3) + ntp * 2 + (g >> 1));

    float C[4][8][4];
#pragma unroll
    for (int a = 0; a < 4; a++)
#pragma unroll
        for (int b = 0; b < 8; b++)
#pragma unroll
            for (int d = 0; d < 4; d++) C[a][b][d] = 0.f;

    auto issue = [&](int kt, int st) {
        const uint32_t sb = smb + st * STAGE_B;
        const int k0 = kt * 32;
#pragma unroll
        for (int i = 0; i < 2; i++)
            cpasync16(sb + aoff[i], aP[i] + k0);
#pragma unroll
        for (int i = 0; i < 4; i++)
            cpasync16(sb + boff[i], bP[i] + (size_t)k0 * NDIM);
    };
    auto compute = [&](int st) {
        const uint32_t sb = smb + st * STAGE_B;
#pragma unroll
        for (int ks = 0; ks < 2; ks++) {
            uint32_t af[4][4];
#pragma unroll
            for (int mt = 0; mt < 4; mt++)
                ldmx4(af[mt], sb + (aFrag[mt] ^ (ks ? 32u : 0u)));
            uint32_t bf[4][4];
#pragma unroll
            for (int ntp = 0; ntp < 4; ntp++)
                ldmx4t(bf[ntp], sb + bFrag[ntp] + ks * 8192);
#pragma unroll
            for (int mt = 0; mt < 4; mt++)
#pragma unroll
                for (int nt = 0; nt < 8; nt++)
                    mma_f16(C[mt][nt], af[mt], bf[nt >> 1][(nt & 1) * 2],
                            bf[nt >> 1][(nt & 1) * 2 + 1]);
        }
    };

    // ---- 4-stage pipeline ----
#pragma unroll
    for (int s = 0; s < NSTAGE - 1; s++) {
        issue(s, s);
        asm volatile("cp.async.commit_group;" ::: "memory");
    }
#pragma unroll 1
    for (int kt = 0; kt < KT; kt++) {
        asm volatile("cp.async.wait_group %0;" :: "n"(NSTAGE - 2) : "memory");
        __syncthreads();
        compute(kt & (NSTAGE - 1));
        if (kt + NSTAGE - 1 < KT)
            issue(kt + NSTAGE - 1, (kt + NSTAGE - 1) & (NSTAGE - 1));
        asm volatile("cp.async.commit_group;" ::: "memory");
    }

    // ---- epilogue ----
    const int grp = lane >> 2, tg = lane & 3;
#pragma unroll
    for (int mt = 0; mt < 4; mt++) {
#pragma unroll
        for (int half = 0; half < 2; half++) {
            const int rowm = wm + mt * 16 + grp + half * 8;
            const int p = row0 + rowm;
            if (p < rowEnd) {
                float wgt = 0.f;
                if (MODE == 2) wgt = g_w[p];
#pragma unroll
                for (int nt = 0; nt < 8; nt++) {
                    float v0 = C[mt][nt][half * 2 + 0];
                    float v1 = C[mt][nt][half * 2 + 1];
                    const int col = n0 + wn + nt * 8 + 2 * tg;
                    if (MODE == 1) {
                        float s0 = v0 / (1.f + __expf(-v0));
                        float s1 = v1 / (1.f + __expf(-v1));
                        *reinterpret_cast<uint32_t*>(&g_hbuf[(size_t)p * FFN + col]) =
                            pk_f16x2(s0, s1);
                    } else {
                        float* dst = g_ybuf +
                            ((size_t)blockIdx.z * NPAIR + p) * HIDDEN + col;
                        *reinterpret_cast<float2*>(dst) = make_float2(v0 * wgt, v1 * wgt);
                    }
                }
            }
        }
    }
}

// ---------------- combine ----------------
__global__ void combine_kernel(float* __restrict__ out) {
    const int t = blockIdx.x;
    const int c = threadIdx.x * 4;
    const int p0 = g_ppos[2 * t], p1 = g_ppos[2 * t + 1];
    float4 acc = make_float4(0.f, 0.f, 0.f, 0.f);
#pragma unroll
    for (int s = 0; s < KSPLIT; s++) {
        const float4 a = *reinterpret_cast<const float4*>(
            g_ybuf + ((size_t)s * NPAIR + p0) * HIDDEN + c);
        const float4 b = *reinterpret_cast<const float4*>(
            g_ybuf + ((size_t)s * NPAIR + p1) * HIDDEN + c);
        acc.x += a.x + b.x; acc.y += a.y + b.y;
        acc.z += a.z + b.z; acc.w += a.w + b.w;
    }
    *reinterpret_cast<float4*>(out + (size_t)t * HIDDEN + c) = acc;
}

// ---------------- launch ----------------
extern "C" void kernel_launch(void* const* d_in, const int* in_sizes, int n_in,
                              void* d_out, int out_size) {
    const float* x   = (const float*)d_in[0];
    const float* rw  = (const float*)d_in[1];
    const float* w1  = (const float*)d_in[2];
    const float* w2  = (const float*)d_in[3];
    const int*   idx = (const int*)d_in[4];
    float* out = (float*)d_out;

    cudaFuncSetAttribute(moe_fp16<1>, cudaFuncAttributeMaxDynamicSharedMemorySize, SMEM_TOTAL);
    cudaFuncSetAttribute(moe_fp16<2>, cudaFuncAttributeMaxDynamicSharedMemorySize, SMEM_TOTAL);

    route_kernel<<<1, 256>>>(idx, rw);
    xconv_kernel<<<(BATCH * HIDDEN) / (256 * 8), 256>>>(x);
    w1conv_kernel<<<8192, 256>>>(w1);
    // GEMM1 (blocks x<40) + fused w2 conversion (blocks 40<=x<56)
    moe_fp16<1><<<dim3(56, FFN / 256, 1), 256, SMEM_TOTAL>>>(w2);
    moe_fp16<2><<<dim3(40, HIDDEN / 256, KSPLIT), 256, SMEM_TOTAL>>>(nullptr);
    combine_kernel<<<BATCH, 256>>>(out);
}

// round 11
// speedup vs baseline: 1.6396x; 1.2236x over previous
#include <cuda_runtime.h>
#include <cuda_fp16.h>
#include <cstdint>
#include <cstddef>

#define BATCH   2048
#define HIDDEN  1024
#define FFN     4096
#define NEXP    8
#define TOPK    2
#define NPAIR   (BATCH * TOPK)
#define MAXMB   64
#define KSPLIT  4

// ---------------- device scratch ----------------
__device__ int    g_off[NEXP + 1];
__device__ int    g_num_mb;
__device__ int    g_blk_e[MAXMB];
__device__ int    g_blk_r0[MAXMB];
__device__ int    g_tok[NPAIR];
__device__ int    g_ppos[NPAIR];
__device__ float  g_w[NPAIR];
__device__ __half g_xh[(size_t)BATCH * HIDDEN];                // 4 MiB
__device__ __half g_w1h[(size_t)NEXP * HIDDEN * FFN];          // 64 MiB fp16 w1
__device__ __half g_w2h[(size_t)NEXP * FFN * HIDDEN];          // 64 MiB fp16 w2
__device__ __half g_hbuf[(size_t)NPAIR * FFN];                 // 32 MiB
__device__ float  g_ybuf[(size_t)KSPLIT * NPAIR * HIDDEN];     // 64 MiB

// ---------------- helpers ----------------
__device__ __forceinline__ uint32_t smem_u32(const void* p) {
    uint32_t a;
    asm("{ .reg .u64 t; cvta.to.shared.u64 t, %1; cvt.u32.u64 %0, t; }" : "=r"(a) : "l"(p));
    return a;
}
__device__ __forceinline__ uint32_t pk_f16x2(float lo, float hi) {
    uint32_t r;
    asm("cvt.rn.f16x2.f32 %0, %1, %2;" : "=r"(r) : "f"(hi), "f"(lo));
    return r;
}
__device__ __forceinline__ void ldmx4(uint32_t* d, uint32_t addr) {
    asm volatile("ldmatrix.sync.aligned.m8n8.x4.shared.b16 {%0,%1,%2,%3}, [%4];"
                 : "=r"(d[0]), "=r"(d[1]), "=r"(d[2]), "=r"(d[3]) : "r"(addr));
}
__device__ __forceinline__ void ldmx4t(uint32_t* d, uint32_t addr) {
    asm volatile("ldmatrix.sync.aligned.m8n8.x4.trans.shared.b16 {%0,%1,%2,%3}, [%4];"
                 : "=r"(d[0]), "=r"(d[1]), "=r"(d[2]), "=r"(d[3]) : "r"(addr));
}
__device__ __forceinline__ void mma_f16(float* c, const uint32_t* a, uint32_t b0, uint32_t b1) {
    asm volatile(
        "mma.sync.aligned.m16n8k16.row.col.f32.f16.f16.f32 "
        "{%0,%1,%2,%3}, {%4,%5,%6,%7}, {%8,%9}, {%0,%1,%2,%3};"
        : "+f"(c[0]), "+f"(c[1]), "+f"(c[2]), "+f"(c[3])
        : "r"(a[0]), "r"(a[1]), "r"(a[2]), "r"(a[3]), "r"(b0), "r"(b1));
}
__device__ __forceinline__ void cpasync16(uint32_t dst, const void* src) {
    asm volatile("cp.async.cg.shared.global [%0], [%1], 16;" :: "r"(dst), "l"(src));
}

// smem per stage (16 KiB):
//   As: 8 KiB fp16 [128 m][32 k]
//   Bs: 8 KiB at +8192 fp16 [32 k][128 n]
__device__ __forceinline__ uint32_t a_addr(int m, int kc) {
    return (uint32_t)((m >> 1) * 128 + (((((m & 1) << 2) | kc) ^ ((m >> 1) & 7)) << 4));
}
__device__ __forceinline__ uint32_t b_addr(int k, int nc) {
    return (uint32_t)(8192 + k * 256 + ((nc ^ (k & 7)) << 4));
}
#define STAGE_B 16384
#define NSTAGE  4
#define SMEM_TOTAL (NSTAGE * STAGE_B)    // 64 KiB

// ---------------- routing (128-row M-blocks) ----------------
__global__ void route_kernel(const int* __restrict__ idx32, const float* __restrict__ rw) {
    __shared__ int s_cnt[NEXP];
    __shared__ int s_fill[NEXP];
    __shared__ int s_off[NEXP + 1];
    __shared__ int s_is64;
    const int tid = threadIdx.x;

    if (tid < NEXP) { s_cnt[tid] = 0; s_fill[tid] = 0; }
    if (tid == 0) {
        int any = 0;
        for (int i = 0; i < 64; i++) any |= idx32[2 * i + 1];
        s_is64 = (any == 0) ? 1 : 0;
    }
    __syncthreads();
    const int is64 = s_is64;

    for (int i = tid; i < NPAIR; i += blockDim.x) {
        int e = is64 ? idx32[2 * i] : idx32[i];
        atomicAdd(&s_cnt[e], 1);
    }
    __syncthreads();

    if (tid == 0) {
        int acc = 0, nb = 0;
        s_off[0] = 0;
        for (int e = 0; e < NEXP; e++) {
            for (int r = 0; r < s_cnt[e]; r += 128) {
                g_blk_e[nb] = e; g_blk_r0[nb] = acc + r; nb++;
            }
            acc += s_cnt[e];
            s_off[e + 1] = acc;
        }
        g_num_mb = nb;
        for (int e = 0; e <= NEXP; e++) g_off[e] = s_off[e];
    }
    __syncthreads();

    for (int i = tid; i < NPAIR; i += blockDim.x) {
        int e = is64 ? idx32[2 * i] : idx32[i];
        int pos = s_off[e] + atomicAdd(&s_fill[e], 1);
        g_tok[pos] = i >> 1;
        g_w[pos]   = rw[i];
        g_ppos[i]  = pos;
    }
}

// ---------------- x -> fp16 ----------------
__global__ void xconv_kernel(const float* __restrict__ x) {
    const size_t i = ((size_t)blockIdx.x * blockDim.x + threadIdx.x) * 8;
    float4 v0 = *reinterpret_cast<const float4*>(x + i);
    float4 v1 = *reinterpret_cast<const float4*>(x + i + 4);
    uint4 o;
    o.x = pk_f16x2(v0.x, v0.y); o.y = pk_f16x2(v0.z, v0.w);
    o.z = pk_f16x2(v1.x, v1.y); o.w = pk_f16x2(v1.z, v1.w);
    *reinterpret_cast<uint4*>(&g_xh[i]) = o;
}

// ---------------- w1 -> fp16 ----------------
__global__ void w1conv_kernel(const float* __restrict__ w) {
    const size_t i = (size_t)blockIdx.x * 1024 + threadIdx.x;
    const float4* s = reinterpret_cast<const float4*>(w);
    uint2* d = reinterpret_cast<uint2*>(g_w1h);
#pragma unroll
    for (int j = 0; j < 4; j++) {
        float4 v = s[i + j * 256];
        uint2 o;
        o.x = pk_f16x2(v.x, v.y); o.y = pk_f16x2(v.z, v.w);
        d[i + j * 256] = o;
    }
}

// ---------------- pure-fp16 grouped GEMM, 4-stage cp.async ----------------
// MODE 1: h[p] = silu(xh[tok(p)] @ w1h[e]); blockIdx.x>=40 => convert w2 slice.
// MODE 2: yb[z][p] = w(p)*(hbuf[p, z*1024:+1024] @ w2h[e][...]).
// CTA tile 128(M) x 128(N), k-tile 32, KT=32. 256 thr = 8 warps (2M x 4N),
// warp tile 64x32. 2 CTAs/SM (regs <= 128). All operands via cp.async (fp16).
template <int MODE>
__global__ __launch_bounds__(256, 2)
void moe_fp16(const float* __restrict__ Wconv) {
    constexpr int NDIM = (MODE == 1) ? FFN : HIDDEN;
    constexpr int KT = 32;

    // -------- fused w2 converter blocks (GEMM1 grid only) --------
    if (MODE == 1 && blockIdx.x >= 40) {
        const int slice = (blockIdx.x - 40) + 8 * blockIdx.y;      // 0..255
        const size_t base4 = (size_t)slice * 32768;                // float4 units
        const float4* s = reinterpret_cast<const float4*>(Wconv) + base4;
        uint2* d = reinterpret_cast<uint2*>(g_w2h) + base4;
        for (int i = threadIdx.x; i < 32768; i += 256) {
            float4 v = s[i];
            uint2 o;
            o.x = pk_f16x2(v.x, v.y); o.y = pk_f16x2(v.z, v.w);
            d[i] = o;
        }
        return;
    }

    extern __shared__ __align__(128) uint8_t sm[];

    const int mb = blockIdx.x;
    if (mb >= g_num_mb) return;
    const int e      = g_blk_e[mb];
    const int row0   = g_blk_r0[mb];
    const int rowEnd = g_off[e + 1];
    const int n0     = blockIdx.y * 128;
    const int kbase  = (MODE == 2) ? blockIdx.z * 1024 : 0;
    const __half* __restrict__ Wh =
        ((MODE == 1) ? g_w1h : g_w2h)
        + (size_t)e * ((MODE == 1) ? HIDDEN : FFN) * NDIM
        + (size_t)kbase * NDIM;

    const int tid = threadIdx.x, lane = tid & 31, warp = tid >> 5;
    const int wm = (warp & 1) * 64, wn = (warp >> 1) * 32;
    const uint32_t smb = smem_u32(sm);

    // ---- A cp.async: 2 units/thread (1 row x 8 k = 16B) ----
    const __half* aP[2];
    uint32_t aoff[2];
#pragma unroll
    for (int i = 0; i < 2; i++) {
        int u = tid + i * 256;            // 0..511
        int m = u >> 2, kc = u & 3;
        int p = row0 + m; if (p >= rowEnd) p = rowEnd - 1;
        aP[i] = ((MODE == 1) ? (g_xh + (size_t)g_tok[p] * HIDDEN)
                             : (g_hbuf + (size_t)p * FFN + kbase)) + kc * 8;
        aoff[i] = a_addr(m, kc);
    }
    // ---- B cp.async: 2 units/thread (1 k x 8 n = 16B) ----
    const __half* bP[2];
    uint32_t boff[2];
#pragma unroll
    for (int i = 0; i < 2; i++) {
        int u = tid + i * 256;            // 0..511
        int k = u >> 4, nc = u & 15;
        bP[i] = Wh + (size_t)k * NDIM + n0 + nc * 8;
        boff[i] = b_addr(k, nc);
    }

    // ---- fragment base addresses (ks=0); ks=1: A ^32, B +4096 ----
    const int g = lane >> 3, r = lane & 7;
    uint32_t aFrag[4], bFrag[2];
#pragma unroll
    for (int mt = 0; mt < 4; mt++)
        aFrag[mt] = a_addr(wm + mt * 16 + (g & 1) * 8 + r, (g >> 1));
#pragma unroll
    for (int ntp = 0; ntp < 2; ntp++)
        bFrag[ntp] = b_addr((g & 1) * 8 + r, (wn >> 3) + ntp * 2 + (g >> 1));

    float C[4][4][4];
#pragma unroll
    for (int a = 0; a < 4; a++)
#pragma unroll
        for (int b = 0; b < 4; b++)
#pragma unroll
            for (int d = 0; d < 4; d++) C[a][b][d] = 0.f;

    auto issue = [&](int kt, int st) {
        const uint32_t sb = smb + st * STAGE_B;
        const int k0 = kt * 32;
#pragma unroll
        for (int i = 0; i < 2; i++)
            cpasync16(sb + aoff[i], aP[i] + k0);
#pragma unroll
        for (int i = 0; i < 2; i++)
            cpasync16(sb + boff[i], bP[i] + (size_t)k0 * NDIM);
    };
    auto compute = [&](int st) {
        const uint32_t sb = smb + st * STAGE_B;
#pragma unroll
        for (int ks = 0; ks < 2; ks++) {
            uint32_t af[4][4];
#pragma unroll
            for (int mt = 0; mt < 4; mt++)
                ldmx4(af[mt], sb + (aFrag[mt] ^ (ks ? 32u : 0u)));
            uint32_t bf[2][4];
#pragma unroll
            for (int ntp = 0; ntp < 2; ntp++)
                ldmx4t(bf[ntp], sb + bFrag[ntp] + ks * 4096);
#pragma unroll
            for (int mt = 0; mt < 4; mt++)
#pragma unroll
                for (int nt = 0; nt < 4; nt++)
                    mma_f16(C[mt][nt], af[mt], bf[nt >> 1][(nt & 1) * 2],
                            bf[nt >> 1][(nt & 1) * 2 + 1]);
        }
    };

    // ---- 4-stage pipeline ----
#pragma unroll
    for (int s = 0; s < NSTAGE - 1; s++) {
        issue(s, s);
        asm volatile("cp.async.commit_group;" ::: "memory");
    }
#pragma unroll 1
    for (int kt = 0; kt < KT; kt++) {
        asm volatile("cp.async.wait_group %0;" :: "n"(NSTAGE - 2) : "memory");
        __syncthreads();
        compute(kt & (NSTAGE - 1));
        if (kt + NSTAGE - 1 < KT)
            issue(kt + NSTAGE - 1, (kt + NSTAGE - 1) & (NSTAGE - 1));
        asm volatile("cp.async.commit_group;" ::: "memory");
    }

    // ---- epilogue ----
    const int grp = lane >> 2, tg = lane & 3;
#pragma unroll
    for (int mt = 0; mt < 4; mt++) {
#pragma unroll
        for (int half = 0; half < 2; half++) {
            const int rowm = wm + mt * 16 + grp + half * 8;
            const int p = row0 + rowm;
            if (p < rowEnd) {
                float wgt = 0.f;
                if (MODE == 2) wgt = g_w[p];
#pragma unroll
                for (int nt = 0; nt < 4; nt++) {
                    float v0 = C[mt][nt][half * 2 + 0];
                    float v1 = C[mt][nt][half * 2 + 1];
                    const int col = n0 + wn + nt * 8 + 2 * tg;
                    if (MODE == 1) {
                        float s0 = v0 / (1.f + __expf(-v0));
                        float s1 = v1 / (1.f + __expf(-v1));
                        *reinterpret_cast<uint32_t*>(&g_hbuf[(size_t)p * FFN + col]) =
                            pk_f16x2(s0, s1);
                    } else {
                        float* dst = g_ybuf +
                            ((size_t)blockIdx.z * NPAIR + p) * HIDDEN + col;
                        *reinterpret_cast<float2*>(dst) = make_float2(v0 * wgt, v1 * wgt);
                    }
                }
            }
        }
    }
}

// ---------------- combine ----------------
__global__ void combine_kernel(float* __restrict__ out) {
    const int t = blockIdx.x;
    const int c = threadIdx.x * 4;
    const int p0 = g_ppos[2 * t], p1 = g_ppos[2 * t + 1];
    float4 acc = make_float4(0.f, 0.f, 0.f, 0.f);
#pragma unroll
    for (int s = 0; s < KSPLIT; s++) {
        const float4 a = *reinterpret_cast<const float4*>(
            g_ybuf + ((size_t)s * NPAIR + p0) * HIDDEN + c);
        const float4 b = *reinterpret_cast<const float4*>(
            g_ybuf + ((size_t)s * NPAIR + p1) * HIDDEN + c);
        acc.x += a.x + b.x; acc.y += a.y + b.y;
        acc.z += a.z + b.z; acc.w += a.w + b.w;
    }
    *reinterpret_cast<float4*>(out + (size_t)t * HIDDEN + c) = acc;
}

// ---------------- launch ----------------
extern "C" void kernel_launch(void* const* d_in, const int* in_sizes, int n_in,
                              void* d_out, int out_size) {
    const float* x   = (const float*)d_in[0];
    const float* rw  = (const float*)d_in[1];
    const float* w1  = (const float*)d_in[2];
    const float* w2  = (const float*)d_in[3];
    const int*   idx = (const int*)d_in[4];
    float* out = (float*)d_out;

    cudaFuncSetAttribute(moe_fp16<1>, cudaFuncAttributeMaxDynamicSharedMemorySize, SMEM_TOTAL);
    cudaFuncSetAttribute(moe_fp16<2>, cudaFuncAttributeMaxDynamicSharedMemorySize, SMEM_TOTAL);

    route_kernel<<<1, 256>>>(idx, rw);
    xconv_kernel<<<(BATCH * HIDDEN) / (256 * 8), 256>>>(x);
    w1conv_kernel<<<8192, 256>>>(w1);
    // GEMM1 (blocks x<40) + fused w2 conversion (blocks 40<=x<48)
    moe_fp16<1><<<dim3(48, FFN / 128, 1), 256, SMEM_TOTAL>>>(w2);
    moe_fp16<2><<<dim3(40, HIDDEN / 128, KSPLIT), 256, SMEM_TOTAL>>>(nullptr);
    combine_kernel<<<BATCH, 256>>>(out);
}

// round 12
// speedup vs baseline: 1.7131x; 1.0448x over previous
#include <cuda_runtime.h>
#include <cuda_fp16.h>
#include <cstdint>
#include <cstddef>

#define BATCH   2048
#define HIDDEN  1024
#define FFN     4096
#define NEXP    8
#define TOPK    2
#define NPAIR   (BATCH * TOPK)
#define MAXMB   64
#define KSPLIT  2

// ---------------- device scratch ----------------
__device__ int    g_off[NEXP + 1];
__device__ int    g_num_mb;
__device__ int    g_blk_e[MAXMB];
__device__ int    g_blk_r0[MAXMB];
__device__ int    g_tok[NPAIR];
__device__ int    g_ppos[NPAIR];
__device__ float  g_w[NPAIR];
__device__ __half g_xh[(size_t)BATCH * HIDDEN];                // 4 MiB
__device__ __half g_w1h[(size_t)NEXP * HIDDEN * FFN];          // 64 MiB fp16 w1
__device__ __half g_w2h[(size_t)NEXP * FFN * HIDDEN];          // 64 MiB fp16 w2
__device__ __half g_hbuf[(size_t)NPAIR * FFN];                 // 32 MiB
__device__ float  g_ybuf[(size_t)KSPLIT * NPAIR * HIDDEN];     // 32 MiB

// ---------------- helpers ----------------
__device__ __forceinline__ uint32_t smem_u32(const void* p) {
    uint32_t a;
    asm("{ .reg .u64 t; cvta.to.shared.u64 t, %1; cvt.u32.u64 %0, t; }" : "=r"(a) : "l"(p));
    return a;
}
__device__ __forceinline__ uint32_t pk_f16x2(float lo, float hi) {
    uint32_t r;
    asm("cvt.rn.f16x2.f32 %0, %1, %2;" : "=r"(r) : "f"(hi), "f"(lo));
    return r;
}
__device__ __forceinline__ void ldmx4(uint32_t* d, uint32_t addr) {
    asm volatile("ldmatrix.sync.aligned.m8n8.x4.shared.b16 {%0,%1,%2,%3}, [%4];"
                 : "=r"(d[0]), "=r"(d[1]), "=r"(d[2]), "=r"(d[3]) : "r"(addr));
}
__device__ __forceinline__ void ldmx4t(uint32_t* d, uint32_t addr) {
    asm volatile("ldmatrix.sync.aligned.m8n8.x4.trans.shared.b16 {%0,%1,%2,%3}, [%4];"
                 : "=r"(d[0]), "=r"(d[1]), "=r"(d[2]), "=r"(d[3]) : "r"(addr));
}
__device__ __forceinline__ void mma_f16(float* c, const uint32_t* a, uint32_t b0, uint32_t b1) {
    asm volatile(
        "mma.sync.aligned.m16n8k16.row.col.f32.f16.f16.f32 "
        "{%0,%1,%2,%3}, {%4,%5,%6,%7}, {%8,%9}, {%0,%1,%2,%3};"
        : "+f"(c[0]), "+f"(c[1]), "+f"(c[2]), "+f"(c[3])
        : "r"(a[0]), "r"(a[1]), "r"(a[2]), "r"(a[3]), "r"(b0), "r"(b1));
}
__device__ __forceinline__ void cpasync16(uint32_t dst, const void* src) {
    asm volatile("cp.async.cg.shared.global [%0], [%1], 16;" :: "r"(dst), "l"(src));
}

// smem per stage (16 KiB): As 8K fp16 [128m][32k]; Bs 8K at +8192 [32k][128n]
__device__ __forceinline__ uint32_t a_addr(int m, int kc) {
    return (uint32_t)((m >> 1) * 128 + (((((m & 1) << 2) | kc) ^ ((m >> 1) & 7)) << 4));
}
__device__ __forceinline__ uint32_t b_addr(int k, int nc) {
    return (uint32_t)(8192 + k * 256 + ((nc ^ (k & 7)) << 4));
}
#define STAGE_B 16384
#define NSTAGE  6
#define SMEM_TOTAL (NSTAGE * STAGE_B)    // 96 KiB per CTA, 192 KiB per SM

// ---------------- routing (128-row M-blocks) ----------------
__global__ void route_kernel(const int* __restrict__ idx32, const float* __restrict__ rw) {
    __shared__ int s_cnt[NEXP];
    __shared__ int s_fill[NEXP];
    __shared__ int s_off[NEXP + 1];
    __shared__ int s_is64;
    const int tid = threadIdx.x;

    if (tid < NEXP) { s_cnt[tid] = 0; s_fill[tid] = 0; }
    if (tid == 0) {
        int any = 0;
        for (int i = 0; i < 64; i++) any |= idx32[2 * i + 1];
        s_is64 = (any == 0) ? 1 : 0;
    }
    __syncthreads();
    const int is64 = s_is64;

    for (int i = tid; i < NPAIR; i += blockDim.x) {
        int e = is64 ? idx32[2 * i] : idx32[i];
        atomicAdd(&s_cnt[e], 1);
    }
    __syncthreads();

    if (tid == 0) {
        int acc = 0, nb = 0;
        s_off[0] = 0;
        for (int e = 0; e < NEXP; e++) {
            for (int r = 0; r < s_cnt[e]; r += 128) {
                g_blk_e[nb] = e; g_blk_r0[nb] = acc + r; nb++;
            }
            acc += s_cnt[e];
            s_off[e + 1] = acc;
        }
        g_num_mb = nb;
        for (int e = 0; e <= NEXP; e++) g_off[e] = s_off[e];
    }
    __syncthreads();

    for (int i = tid; i < NPAIR; i += blockDim.x) {
        int e = is64 ? idx32[2 * i] : idx32[i];
        int pos = s_off[e] + atomicAdd(&s_fill[e], 1);
        g_tok[pos] = i >> 1;
        g_w[pos]   = rw[i];
        g_ppos[i]  = pos;
    }
}

// ---------------- x -> fp16 ----------------
__global__ void xconv_kernel(const float* __restrict__ x) {
    const size_t i = ((size_t)blockIdx.x * blockDim.x + threadIdx.x) * 8;
    float4 v0 = *reinterpret_cast<const float4*>(x + i);
    float4 v1 = *reinterpret_cast<const float4*>(x + i + 4);
    uint4 o;
    o.x = pk_f16x2(v0.x, v0.y); o.y = pk_f16x2(v0.z, v0.w);
    o.z = pk_f16x2(v1.x, v1.y); o.w = pk_f16x2(v1.z, v1.w);
    *reinterpret_cast<uint4*>(&g_xh[i]) = o;
}

// ---------------- w1 -> fp16 ----------------
__global__ void w1conv_kernel(const float* __restrict__ w) {
    const size_t i = (size_t)blockIdx.x * 1024 + threadIdx.x;
    const float4* s = reinterpret_cast<const float4*>(w);
    uint2* d = reinterpret_cast<uint2*>(g_w1h);
#pragma unroll
    for (int j = 0; j < 4; j++) {
        float4 v = s[i + j * 256];
        uint2 o;
        o.x = pk_f16x2(v.x, v.y); o.y = pk_f16x2(v.z, v.w);
        d[i + j * 256] = o;
    }
}

// ---------------- pure-fp16 grouped GEMM, 6-stage cp.async ----------------
// MODE 1: h[p] = silu(xh[tok(p)] @ w1h[e]); blockIdx.x>=40 => convert w2 slice.
// MODE 2: yb[z][p] = w(p)*(hbuf[p, z*2048:+2048] @ w2h[e][...]),  KT=64.
// CTA tile 128(M) x 128(N), k-tile 32. 256 thr = 8 warps (2M x 4N),
// warp tile 64x32. 2 CTAs/SM (regs <= 128). All operands via cp.async (fp16).
template <int MODE, int KT>
__global__ __launch_bounds__(256, 2)
void moe_fp16(const float* __restrict__ Wconv) {
    constexpr int NDIM = (MODE == 1) ? FFN : HIDDEN;

    // -------- fused w2 converter blocks (GEMM1 grid only) --------
    if (MODE == 1 && blockIdx.x >= 40) {
        const int slice = (blockIdx.x - 40) + 8 * blockIdx.y;      // 0..255
        const size_t base4 = (size_t)slice * 32768;                // float4 units
        const float4* s = reinterpret_cast<const float4*>(Wconv) + base4;
        uint2* d = reinterpret_cast<uint2*>(g_w2h) + base4;
        for (int i = threadIdx.x; i < 32768; i += 256) {
            float4 v = s[i];
            uint2 o;
            o.x = pk_f16x2(v.x, v.y); o.y = pk_f16x2(v.z, v.w);
            d[i] = o;
        }
        return;
    }

    extern __shared__ __align__(128) uint8_t sm[];

    const int mb = blockIdx.x;
    if (mb >= g_num_mb) return;
    const int e      = g_blk_e[mb];
    const int row0   = g_blk_r0[mb];
    const int rowEnd = g_off[e + 1];
    const int n0     = blockIdx.y * 128;
    const int kbase  = (MODE == 2) ? blockIdx.z * (KT * 32) : 0;
    const __half* __restrict__ Wh =
        ((MODE == 1) ? g_w1h : g_w2h)
        + (size_t)e * ((MODE == 1) ? HIDDEN : FFN) * NDIM
        + (size_t)kbase * NDIM;

    const int tid = threadIdx.x, lane = tid & 31, warp = tid >> 5;
    const int wm = (warp & 1) * 64, wn = (warp >> 1) * 32;
    const uint32_t smb = smem_u32(sm);

    // ---- A cp.async: 2 units/thread (1 row x 8 k = 16B) ----
    const __half* aP[2];
    uint32_t aoff[2];
#pragma unroll
    for (int i = 0; i < 2; i++) {
        int u = tid + i * 256;            // 0..511
        int m = u >> 2, kc = u & 3;
        int p = row0 + m; if (p >= rowEnd) p = rowEnd - 1;
        aP[i] = ((MODE == 1) ? (g_xh + (size_t)g_tok[p] * HIDDEN)
                             : (g_hbuf + (size_t)p * FFN + kbase)) + kc * 8;
        aoff[i] = a_addr(m, kc);
    }
    // ---- B cp.async: 2 units/thread (1 k x 8 n = 16B) ----
    const __half* bP[2];
    uint32_t boff[2];
#pragma unroll
    for (int i = 0; i < 2; i++) {
        int u = tid + i * 256;            // 0..511
        int k = u >> 4, nc = u & 15;
        bP[i] = Wh + (size_t)k * NDIM + n0 + nc * 8;
        boff[i] = b_addr(k, nc);
    }

    // ---- fragment base addresses (ks=0); ks=1: A ^32, B +4096 ----
    const int g = lane >> 3, r = lane & 7;
    uint32_t aFrag[4], bFrag[2];
#pragma unroll
    for (int mt = 0; mt < 4; mt++)
        aFrag[mt] = a_addr(wm + mt * 16 + (g & 1) * 8 + r, (g >> 1));
#pragma unroll
    for (int ntp = 0; ntp < 2; ntp++)
        bFrag[ntp] = b_addr((g & 1) * 8 + r, (wn >> 3) + ntp * 2 + (g >> 1));

    float C[4][4][4];
#pragma unroll
    for (int a = 0; a < 4; a++)
#pragma unroll
        for (int b = 0; b < 4; b++)
#pragma unroll
            for (int d = 0; d < 4; d++) C[a][b][d] = 0.f;

    auto issue = [&](int kt, int st) {
        const uint32_t sb = smb + st * STAGE_B;
        const int k0 = kt * 32;
#pragma unroll
        for (int i = 0; i < 2; i++)
            cpasync16(sb + aoff[i], aP[i] + k0);
#pragma unroll
        for (int i = 0; i < 2; i++)
            cpasync16(sb + boff[i], bP[i] + (size_t)k0 * NDIM);
    };
    auto compute = [&](int st) {
        const uint32_t sb = smb + st * STAGE_B;
#pragma unroll
        for (int ks = 0; ks < 2; ks++) {
            uint32_t af[4][4];
#pragma unroll
            for (int mt = 0; mt < 4; mt++)
                ldmx4(af[mt], sb + (aFrag[mt] ^ (ks ? 32u : 0u)));
            uint32_t bf[2][4];
#pragma unroll
            for (int ntp = 0; ntp < 2; ntp++)
                ldmx4t(bf[ntp], sb + bFrag[ntp] + ks * 4096);
#pragma unroll
            for (int mt = 0; mt < 4; mt++)
#pragma unroll
                for (int nt = 0; nt < 4; nt++)
                    mma_f16(C[mt][nt], af[mt], bf[nt >> 1][(nt & 1) * 2],
                            bf[nt >> 1][(nt & 1) * 2 + 1]);
        }
    };

    // ---- 6-stage pipeline (rotating stage counters, no modulo) ----
#pragma unroll
    for (int s = 0; s < NSTAGE - 1; s++) {
        issue(s, s);
        asm volatile("cp.async.commit_group;" ::: "memory");
    }
    int st_c = 0, st_i = NSTAGE - 1;
#pragma unroll 1
    for (int kt = 0; kt < KT; kt++) {
        asm volatile("cp.async.wait_group %0;" :: "n"(NSTAGE - 2) : "memory");
        __syncthreads();
        compute(st_c);
        if (++st_c == NSTAGE) st_c = 0;
        if (kt + NSTAGE - 1 < KT) {
            issue(kt + NSTAGE - 1, st_i);
            if (++st_i == NSTAGE) st_i = 0;
        }
        asm volatile("cp.async.commit_group;" ::: "memory");
    }

    // ---- epilogue ----
    const int grp = lane >> 2, tg = lane & 3;
#pragma unroll
    for (int mt = 0; mt < 4; mt++) {
#pragma unroll
        for (int half = 0; half < 2; half++) {
            const int rowm = wm + mt * 16 + grp + half * 8;
            const int p = row0 + rowm;
            if (p < rowEnd) {
                float wgt = 0.f;
                if (MODE == 2) wgt = g_w[p];
#pragma unroll
                for (int nt = 0; nt < 4; nt++) {
                    float v0 = C[mt][nt][half * 2 + 0];
                    float v1 = C[mt][nt][half * 2 + 1];
                    const int col = n0 + wn + nt * 8 + 2 * tg;
                    if (MODE == 1) {
                        float s0 = v0 / (1.f + __expf(-v0));
                        float s1 = v1 / (1.f + __expf(-v1));
                        *reinterpret_cast<uint32_t*>(&g_hbuf[(size_t)p * FFN + col]) =
                            pk_f16x2(s0, s1);
                    } else {
                        float* dst = g_ybuf +
                            ((size_t)blockIdx.z * NPAIR + p) * HIDDEN + col;
                        *reinterpret_cast<float2*>(dst) = make_float2(v0 * wgt, v1 * wgt);
                    }
                }
            }
        }
    }
}

// ---------------- combine ----------------
__global__ void combine_kernel(float* __restrict__ out) {
    const int t = blockIdx.x;
    const int c = threadIdx.x * 4;
    const int p0 = g_ppos[2 * t], p1 = g_ppos[2 * t + 1];
    float4 acc = make_float4(0.f, 0.f, 0.f, 0.f);
#pragma unroll
    for (int s = 0; s < KSPLIT; s++) {
        const float4 a = *reinterpret_cast<const float4*>(
            g_ybuf + ((size_t)s * NPAIR + p0) * HIDDEN + c);
        const float4 b = *reinterpret_cast<const float4*>(
            g_ybuf + ((size_t)s * NPAIR + p1) * HIDDEN + c);
        acc.x += a.x + b.x; acc.y += a.y + b.y;
        acc.z += a.z + b.z; acc.w += a.w + b.w;
    }
    *reinterpret_cast<float4*>(out + (size_t)t * HIDDEN + c) = acc;
}

// ---------------- launch ----------------
extern "C" void kernel_launch(void* const* d_in, const int* in_sizes, int n_in,
                              void* d_out, int out_size) {
    const float* x   = (const float*)d_in[0];
    const float* rw  = (const float*)d_in[1];
    const float* w1  = (const float*)d_in[2];
    const float* w2  = (const float*)d_in[3];
    const int*   idx = (const int*)d_in[4];
    float* out = (float*)d_out;

    cudaFuncSetAttribute(moe_fp16<1, 32>, cudaFuncAttributeMaxDynamicSharedMemorySize, SMEM_TOTAL);
    cudaFuncSetAttribute(moe_fp16<2, 64>, cudaFuncAttributeMaxDynamicSharedMemorySize, SMEM_TOTAL);

    route_kernel<<<1, 256>>>(idx, rw);
    xconv_kernel<<<(BATCH * HIDDEN) / (256 * 8), 256>>>(x);
    w1conv_kernel<<<8192, 256>>>(w1);
    // GEMM1 (blocks x<40) + fused w2 conversion (blocks 40<=x<48)
    moe_fp16<1, 32><<<dim3(48, FFN / 128, 1), 256, SMEM_TOTAL>>>(w2);
    moe_fp16<2, 64><<<dim3(40, HIDDEN / 128, KSPLIT), 256, SMEM_TOTAL>>>(nullptr);
    combine_kernel<<<BATCH, 256>>>(out);
}

// round 13
// speedup vs baseline: 1.7606x; 1.0277x over previous
#include <cuda_runtime.h>
#include <cuda_fp16.h>
#include <cstdint>
#include <cstddef>

#define BATCH   2048
#define HIDDEN  1024
#define FFN     4096
#define NEXP    8
#define TOPK    2
#define NPAIR   (BATCH * TOPK)
#define MAXMB   64
#define KSPLIT  2

// ---------------- device scratch ----------------
__device__ int    g_off[NEXP + 1];
__device__ int    g_num_mb;
__device__ int    g_blk_e[MAXMB];
__device__ int    g_blk_r0[MAXMB];
__device__ int    g_tok[NPAIR];
__device__ int    g_ppos[NPAIR];
__device__ float  g_w[NPAIR];
__device__ __half g_xh[(size_t)BATCH * HIDDEN];                // 4 MiB
__device__ __half g_w1h[(size_t)NEXP * HIDDEN * FFN];          // 64 MiB fp16 w1
__device__ __half g_w2h[(size_t)NEXP * FFN * HIDDEN];          // 64 MiB fp16 w2
__device__ __half g_hbuf[(size_t)NPAIR * FFN];                 // 32 MiB
__device__ float  g_ybuf[(size_t)KSPLIT * NPAIR * HIDDEN];     // 32 MiB

// ---------------- helpers ----------------
__device__ __forceinline__ uint32_t smem_u32(const void* p) {
    uint32_t a;
    asm("{ .reg .u64 t; cvta.to.shared.u64 t, %1; cvt.u32.u64 %0, t; }" : "=r"(a) : "l"(p));
    return a;
}
__device__ __forceinline__ uint32_t pk_f16x2(float lo, float hi) {
    uint32_t r;
    asm("cvt.rn.f16x2.f32 %0, %1, %2;" : "=r"(r) : "f"(hi), "f"(lo));
    return r;
}
__device__ __forceinline__ void ldmx4(uint32_t* d, uint32_t addr) {
    asm volatile("ldmatrix.sync.aligned.m8n8.x4.shared.b16 {%0,%1,%2,%3}, [%4];"
                 : "=r"(d[0]), "=r"(d[1]), "=r"(d[2]), "=r"(d[3]) : "r"(addr));
}
__device__ __forceinline__ void ldmx4t(uint32_t* d, uint32_t addr) {
    asm volatile("ldmatrix.sync.aligned.m8n8.x4.trans.shared.b16 {%0,%1,%2,%3}, [%4];"
                 : "=r"(d[0]), "=r"(d[1]), "=r"(d[2]), "=r"(d[3]) : "r"(addr));
}
__device__ __forceinline__ void mma_f16(float* c, const uint32_t* a, uint32_t b0, uint32_t b1) {
    asm volatile(
        "mma.sync.aligned.m16n8k16.row.col.f32.f16.f16.f32 "
        "{%0,%1,%2,%3}, {%4,%5,%6,%7}, {%8,%9}, {%0,%1,%2,%3};"
        : "+f"(c[0]), "+f"(c[1]), "+f"(c[2]), "+f"(c[3])
        : "r"(a[0]), "r"(a[1]), "r"(a[2]), "r"(a[3]), "r"(b0), "r"(b1));
}
__device__ __forceinline__ void cpasync16(uint32_t dst, const void* src) {
    asm volatile("cp.async.cg.shared.global [%0], [%1], 16;" :: "r"(dst), "l"(src));
}

// smem per stage (32 KiB), k-tile 64:
//   As: 16 KiB fp16 [128 m][64 k], 128B rows, SW128: m*128 + ((kc ^ (m&7))<<4)
//   Bs: 16 KiB at +16384 fp16 [64 k][128 n]: k*256 + ((nc ^ (k&7))<<4)
__device__ __forceinline__ uint32_t a_addr(int m, int kc) {
    return (uint32_t)(m * 128 + ((kc ^ (m & 7)) << 4));
}
__device__ __forceinline__ uint32_t b_addr(int k, int nc) {
    return (uint32_t)(16384 + k * 256 + ((nc ^ (k & 7)) << 4));
}
#define STAGE_B 32768
#define NSTAGE  3
#define SMEM_TOTAL (NSTAGE * STAGE_B)    // 96 KiB per CTA, 192 KiB per SM

// ---------------- routing (128-row M-blocks) ----------------
__global__ void route_kernel(const int* __restrict__ idx32, const float* __restrict__ rw) {
    __shared__ int s_cnt[NEXP];
    __shared__ int s_fill[NEXP];
    __shared__ int s_off[NEXP + 1];
    __shared__ int s_is64;
    const int tid = threadIdx.x;

    if (tid < NEXP) { s_cnt[tid] = 0; s_fill[tid] = 0; }
    if (tid == 0) {
        int any = 0;
        for (int i = 0; i < 64; i++) any |= idx32[2 * i + 1];
        s_is64 = (any == 0) ? 1 : 0;
    }
    __syncthreads();
    const int is64 = s_is64;

    for (int i = tid; i < NPAIR; i += blockDim.x) {
        int e = is64 ? idx32[2 * i] : idx32[i];
        atomicAdd(&s_cnt[e], 1);
    }
    __syncthreads();

    if (tid == 0) {
        int acc = 0, nb = 0;
        s_off[0] = 0;
        for (int e = 0; e < NEXP; e++) {
            for (int r = 0; r < s_cnt[e]; r += 128) {
                g_blk_e[nb] = e; g_blk_r0[nb] = acc + r; nb++;
            }
            acc += s_cnt[e];
            s_off[e + 1] = acc;
        }
        g_num_mb = nb;
        for (int e = 0; e <= NEXP; e++) g_off[e] = s_off[e];
    }
    __syncthreads();

    for (int i = tid; i < NPAIR; i += blockDim.x) {
        int e = is64 ? idx32[2 * i] : idx32[i];
        int pos = s_off[e] + atomicAdd(&s_fill[e], 1);
        g_tok[pos] = i >> 1;
        g_w[pos]   = rw[i];
        g_ppos[i]  = pos;
    }
}

// ---------------- x -> fp16 ----------------
__global__ void xconv_kernel(const float* __restrict__ x) {
    const size_t i = ((size_t)blockIdx.x * blockDim.x + threadIdx.x) * 8;
    float4 v0 = *reinterpret_cast<const float4*>(x + i);
    float4 v1 = *reinterpret_cast<const float4*>(x + i + 4);
    uint4 o;
    o.x = pk_f16x2(v0.x, v0.y); o.y = pk_f16x2(v0.z, v0.w);
    o.z = pk_f16x2(v1.x, v1.y); o.w = pk_f16x2(v1.z, v1.w);
    *reinterpret_cast<uint4*>(&g_xh[i]) = o;
}

// ---------------- w1 -> fp16 ----------------
__global__ void w1conv_kernel(const float* __restrict__ w) {
    const size_t i = (size_t)blockIdx.x * 1024 + threadIdx.x;
    const float4* s = reinterpret_cast<const float4*>(w);
    uint2* d = reinterpret_cast<uint2*>(g_w1h);
#pragma unroll
    for (int j = 0; j < 4; j++) {
        float4 v = s[i + j * 256];
        uint2 o;
        o.x = pk_f16x2(v.x, v.y); o.y = pk_f16x2(v.z, v.w);
        d[i + j * 256] = o;
    }
}

// ---------------- pure-fp16 grouped GEMM, k-tile 64, 3-stage cp.async ----------------
// MODE 1: h[p] = silu(xh[tok(p)] @ w1h[e]); blockIdx.x>=40 => convert w2 slice.
// MODE 2: yb[z][p] = w(p)*(hbuf[p, z*2048:+2048] @ w2h[e][...]).
// CTA tile 128(M) x 128(N), k-tile 64. 256 thr = 8 warps (2M x 4N),
// warp tile 64x32. 2 CTAs/SM (regs <= 128). All operands via cp.async (fp16).
template <int MODE, int KT>
__global__ __launch_bounds__(256, 2)
void moe_fp16(const float* __restrict__ Wconv) {
    constexpr int NDIM = (MODE == 1) ? FFN : HIDDEN;

    // -------- fused w2 converter blocks (GEMM1 grid only) --------
    if (MODE == 1 && blockIdx.x >= 40) {
        const int slice = (blockIdx.x - 40) + 8 * blockIdx.y;      // 0..255
        const size_t base4 = (size_t)slice * 32768;                // float4 units
        const float4* s = reinterpret_cast<const float4*>(Wconv) + base4;
        uint2* d = reinterpret_cast<uint2*>(g_w2h) + base4;
        for (int i = threadIdx.x; i < 32768; i += 256) {
            float4 v = s[i];
            uint2 o;
            o.x = pk_f16x2(v.x, v.y); o.y = pk_f16x2(v.z, v.w);
            d[i] = o;
        }
        return;
    }

    extern __shared__ __align__(128) uint8_t sm[];

    const int mb = blockIdx.x;
    if (mb >= g_num_mb) return;
    const int e      = g_blk_e[mb];
    const int row0   = g_blk_r0[mb];
    const int rowEnd = g_off[e + 1];
    const int n0     = blockIdx.y * 128;
    const int kbase  = (MODE == 2) ? blockIdx.z * (KT * 64) : 0;
    const __half* __restrict__ Wh =
        ((MODE == 1) ? g_w1h : g_w2h)
        + (size_t)e * ((MODE == 1) ? HIDDEN : FFN) * NDIM
        + (size_t)kbase * NDIM;

    const int tid = threadIdx.x, lane = tid & 31, warp = tid >> 5;
    const int wm = (warp & 1) * 64, wn = (warp >> 1) * 32;
    const uint32_t smb = smem_u32(sm);

    // ---- A cp.async: 4 units/thread (1 row x 8 k = 16B); tile 128m x 64k ----
    const __half* aP[4];
    uint32_t aoff[4];
#pragma unroll
    for (int i = 0; i < 4; i++) {
        int u = tid + i * 256;            // 0..1023
        int m = u >> 3, kc = u & 7;
        int p = row0 + m; if (p >= rowEnd) p = rowEnd - 1;
        aP[i] = ((MODE == 1) ? (g_xh + (size_t)g_tok[p] * HIDDEN)
                             : (g_hbuf + (size_t)p * FFN + kbase)) + kc * 8;
        aoff[i] = a_addr(m, kc);
    }
    // ---- B cp.async: 4 units/thread (1 k x 8 n = 16B); tile 64k x 128n ----
    const __half* bP[4];
    uint32_t boff[4];
#pragma unroll
    for (int i = 0; i < 4; i++) {
        int u = tid + i * 256;            // 0..1023
        int k = u >> 4, nc = u & 15;
        bP[i] = Wh + (size_t)k * NDIM + n0 + nc * 8;
        boff[i] = b_addr(k, nc);
    }

    // ---- fragment base addresses (ks=0) ----
    // A per ks: kc = (g>>1) | (ks<<1); no carry => addr ^ (ks<<5).
    // B per ks: k += 16*ks => addr + ks*4096 (k&7 unchanged).
    const int g = lane >> 3, r = lane & 7;
    uint32_t aFrag[4], bFrag[2];
#pragma unroll
    for (int mt = 0; mt < 4; mt++)
        aFrag[mt] = a_addr(wm + mt * 16 + (g & 1) * 8 + r, (g >> 1));
#pragma unroll
    for (int ntp = 0; ntp < 2; ntp++)
        bFrag[ntp] = b_addr((g & 1) * 8 + r, (wn >> 3) + ntp * 2 + (g >> 1));

    float C[4][4][4];
#pragma unroll
    for (int a = 0; a < 4; a++)
#pragma unroll
        for (int b = 0; b < 4; b++)
#pragma unroll
            for (int d = 0; d < 4; d++) C[a][b][d] = 0.f;

    auto issue = [&](int kt, int st) {
        const uint32_t sb = smb + st * STAGE_B;
        const int k0 = kt * 64;
#pragma unroll
        for (int i = 0; i < 4; i++)
            cpasync16(sb + aoff[i], aP[i] + k0);
#pragma unroll
        for (int i = 0; i < 4; i++)
            cpasync16(sb + boff[i], bP[i] + (size_t)k0 * NDIM);
    };
    auto compute = [&](int st) {
        const uint32_t sb = smb + st * STAGE_B;
#pragma unroll
        for (int ks = 0; ks < 4; ks++) {
            uint32_t af[4][4];
#pragma unroll
            for (int mt = 0; mt < 4; mt++)
                ldmx4(af[mt], sb + (aFrag[mt] ^ (uint32_t)(ks << 5)));
            uint32_t bf[2][4];
#pragma unroll
            for (int ntp = 0; ntp < 2; ntp++)
                ldmx4t(bf[ntp], sb + bFrag[ntp] + ks * 4096);
#pragma unroll
            for (int mt = 0; mt < 4; mt++)
#pragma unroll
                for (int nt = 0; nt < 4; nt++)
                    mma_f16(C[mt][nt], af[mt], bf[nt >> 1][(nt & 1) * 2],
                            bf[nt >> 1][(nt & 1) * 2 + 1]);
        }
    };

    // ---- 3-stage pipeline ----
#pragma unroll
    for (int s = 0; s < NSTAGE - 1; s++) {
        issue(s, s);
        asm volatile("cp.async.commit_group;" ::: "memory");
    }
    int st_c = 0, st_i = NSTAGE - 1;
#pragma unroll 1
    for (int kt = 0; kt < KT; kt++) {
        asm volatile("cp.async.wait_group %0;" :: "n"(NSTAGE - 2) : "memory");
        __syncthreads();
        compute(st_c);
        if (++st_c == NSTAGE) st_c = 0;
        if (kt + NSTAGE - 1 < KT) {
            issue(kt + NSTAGE - 1, st_i);
            if (++st_i == NSTAGE) st_i = 0;
        }
        asm volatile("cp.async.commit_group;" ::: "memory");
    }

    // ---- epilogue ----
    const int grp = lane >> 2, tg = lane & 3;
#pragma unroll
    for (int mt = 0; mt < 4; mt++) {
#pragma unroll
        for (int half = 0; half < 2; half++) {
            const int rowm = wm + mt * 16 + grp + half * 8;
            const int p = row0 + rowm;
            if (p < rowEnd) {
                float wgt = 0.f;
                if (MODE == 2) wgt = g_w[p];
#pragma unroll
                for (int nt = 0; nt < 4; nt++) {
                    float v0 = C[mt][nt][half * 2 + 0];
                    float v1 = C[mt][nt][half * 2 + 1];
                    const int col = n0 + wn + nt * 8 + 2 * tg;
                    if (MODE == 1) {
                        float s0 = v0 / (1.f + __expf(-v0));
                        float s1 = v1 / (1.f + __expf(-v1));
                        *reinterpret_cast<uint32_t*>(&g_hbuf[(size_t)p * FFN + col]) =
                            pk_f16x2(s0, s1);
                    } else {
                        float* dst = g_ybuf +
                            ((size_t)blockIdx.z * NPAIR + p) * HIDDEN + col;
                        *reinterpret_cast<float2*>(dst) = make_float2(v0 * wgt, v1 * wgt);
                    }
                }
            }
        }
    }
}

// ---------------- combine ----------------
__global__ void combine_kernel(float* __restrict__ out) {
    const int t = blockIdx.x;
    const int c = threadIdx.x * 4;
    const int p0 = g_ppos[2 * t], p1 = g_ppos[2 * t + 1];
    float4 acc = make_float4(0.f, 0.f, 0.f, 0.f);
#pragma unroll
    for (int s = 0; s < KSPLIT; s++) {
        const float4 a = *reinterpret_cast<const float4*>(
            g_ybuf + ((size_t)s * NPAIR + p0) * HIDDEN + c);
        const float4 b = *reinterpret_cast<const float4*>(
            g_ybuf + ((size_t)s * NPAIR + p1) * HIDDEN + c);
        acc.x += a.x + b.x; acc.y += a.y + b.y;
        acc.z += a.z + b.z; acc.w += a.w + b.w;
    }
    *reinterpret_cast<float4*>(out + (size_t)t * HIDDEN + c) = acc;
}

// ---------------- launch ----------------
extern "C" void kernel_launch(void* const* d_in, const int* in_sizes, int n_in,
                              void* d_out, int out_size) {
    const float* x   = (const float*)d_in[0];
    const float* rw  = (const float*)d_in[1];
    const float* w1  = (const float*)d_in[2];
    const float* w2  = (const float*)d_in[3];
    const int*   idx = (const int*)d_in[4];
    float* out = (float*)d_out;

    cudaFuncSetAttribute(moe_fp16<1, 16>, cudaFuncAttributeMaxDynamicSharedMemorySize, SMEM_TOTAL);
    cudaFuncSetAttribute(moe_fp16<2, 32>, cudaFuncAttributeMaxDynamicSharedMemorySize, SMEM_TOTAL);

    route_kernel<<<1, 256>>>(idx, rw);
    xconv_kernel<<<(BATCH * HIDDEN) / (256 * 8), 256>>>(x);
    w1conv_kernel<<<8192, 256>>>(w1);
    // GEMM1 (blocks x<40) + fused w2 conversion (blocks 40<=x<48)
    moe_fp16<1, 16><<<dim3(48, FFN / 128, 1), 256, SMEM_TOTAL>>>(w2);
    moe_fp16<2, 32><<<dim3(40, HIDDEN / 128, KSPLIT), 256, SMEM_TOTAL>>>(nullptr);
    combine_kernel<<<BATCH, 256>>>(out);
}